// round 17
// baseline (speedup 1.0000x reference)
#include <cuda_runtime.h>
#include <cuda_fp16.h>
#include <math.h>

#define NN   100000
#define EE   1600000
#define DIN  128
#define HD   64      // HEADS*HID
#define HEADS 4
#define HID  16
#define DOUT 32
#define NEG  0.2f
#define NBLK ((NN + 1023) / 1024)   // scan blocks = 98
#define XA_STRIDE 136               // halves, padded
#define WB_STRIDE 72                // halves, padded
#define G1_SMEM ((128 * XA_STRIDE + DIN * WB_STRIDE) * 2)   // 53248 B
#define FULLM 0xffffffffu

typedef unsigned long long u64;

// ---------------- scratch (device globals; no allocation allowed) ----------
__device__ __align__(16) __half g_h1h[NN * HD];     // x @ W1   (fp16 storage)
__device__ __align__(16) float g_als1[NN * HEADS];
__device__ __align__(16) float g_ald1[NN * HEADS];
__device__ __align__(16) __half g_t2h[NN * DOUT];   // feat1 @ W2 (fp16 storage)
__device__ __align__(16) float g_als2[NN];
__device__ __align__(16) float g_ald2[NN];
// CSR scratch
__device__ __align__(16) int g_rank[EE];            // per-dst arrival rank
__device__ int g_cnt[NN];
__device__ int g_indptr[NN + 1];                    // block-local exclusive scan
__device__ int g_boff[NBLK];                        // per-block offsets (for gathers)
__device__ int g_indices[EE];
__device__ int g_bsum[NBLK];

__global__ void gemm1_kernel(const float*, const float*, const float*, const float*);

// ---------------- stream/event for fork-join overlap (created pre-main) ----
static cudaStream_t g_s2;
static cudaEvent_t g_evFork, g_evJoin;
static struct Boot {
    Boot() {
        cudaStreamCreateWithFlags(&g_s2, cudaStreamNonBlocking);
        cudaEventCreateWithFlags(&g_evFork, cudaEventDisableTiming);
        cudaEventCreateWithFlags(&g_evJoin, cudaEventDisableTiming);
        cudaFuncSetAttribute(gemm1_kernel,
                             cudaFuncAttributeMaxDynamicSharedMemorySize, G1_SMEM);
    }
} g_boot;

__device__ __forceinline__ float lrelu_exp(float l) {
    l = fmaxf(l, NEG * l);                // branchless leaky relu
    return __expf(fminf(l, 25.f));        // clamp is a no-op safety net
}

// per-block dtype self-detect: 8 int64 probes (int32 data -> huge values)
__device__ __forceinline__ int block_detect_is64(const long long* ei, int* sflag) {
    if (threadIdx.x == 0) {
        int ok = 1;
        #pragma unroll
        for (int k = 0; k < 8; k++) {
            long long v = ei[k];
            if (v < 0 || v >= NN) { ok = 0; break; }
        }
        *sflag = ok;
    }
    __syncthreads();
    return *sflag;
}

// ---- tensor-core primitives ----------------------------------------------
__device__ __forceinline__ void ldsm_x4(unsigned& r0, unsigned& r1, unsigned& r2, unsigned& r3,
                                        unsigned addr) {
    asm volatile("ldmatrix.sync.aligned.m8n8.x4.shared.b16 {%0,%1,%2,%3}, [%4];"
                 : "=r"(r0), "=r"(r1), "=r"(r2), "=r"(r3) : "r"(addr));
}
__device__ __forceinline__ void ldsm_x2t(unsigned& r0, unsigned& r1, unsigned addr) {
    asm volatile("ldmatrix.sync.aligned.m8n8.x2.trans.shared.b16 {%0,%1}, [%2];"
                 : "=r"(r0), "=r"(r1) : "r"(addr));
}
__device__ __forceinline__ void mma16816(float* c,
        unsigned a0, unsigned a1, unsigned a2, unsigned a3,
        unsigned b0, unsigned b1) {
    asm volatile("mma.sync.aligned.m16n8k16.row.col.f32.f16.f16.f32 "
                 "{%0,%1,%2,%3}, {%4,%5,%6,%7}, {%8,%9}, {%0,%1,%2,%3};"
                 : "+f"(c[0]), "+f"(c[1]), "+f"(c[2]), "+f"(c[3])
                 : "r"(a0), "r"(a1), "r"(a2), "r"(a3), "r"(b0), "r"(b1));
}

// ---------------- count + rank (2 edges/thread; self-detect) ---------------
__global__ void convert_count_kernel(const long long* __restrict__ ei) {
    __shared__ int sflag;
    int is64 = block_detect_is64(ei, &sflag);
    int e = (blockIdx.x * blockDim.x + threadIdx.x) * 2;
    if (e >= EE) return;
    int d0, d1;
    if (is64) {
        longlong2 dv = *(const longlong2*)&ei[e + EE];
        d0 = (int)dv.x; d1 = (int)dv.y;
    } else {
        const int* p = (const int*)ei;
        int2 dv = *(const int2*)&p[e + EE];
        d0 = dv.x; d1 = dv.y;
    }
    int r0 = atomicAdd(&g_cnt[d0], 1);
    int r1 = atomicAdd(&g_cnt[d1], 1);
    *(int2*)&g_rank[e] = make_int2(r0, r1);
}

// ---------------- scan phase 1: per-block exclusive scan -------------------
__global__ void scan1_kernel() {
    __shared__ int wsum[32];
    int t = threadIdx.x;
    int i = blockIdx.x * 1024 + t;
    int v = (i < NN) ? g_cnt[i] : 0;
    int lane = t & 31, wid = t >> 5;
    int p = v;
    #pragma unroll
    for (int off = 1; off < 32; off <<= 1) {
        int a = __shfl_up_sync(FULLM, p, off);
        if (lane >= off) p += a;
    }
    if (lane == 31) wsum[wid] = p;
    __syncthreads();
    if (wid == 0) {
        int s = wsum[lane];
        #pragma unroll
        for (int off = 1; off < 32; off <<= 1) {
            int a = __shfl_up_sync(FULLM, s, off);
            if (lane >= off) s += a;
        }
        wsum[lane] = s;
    }
    __syncthreads();
    int base = (wid > 0) ? wsum[wid - 1] : 0;
    int incl = p + base;
    if (i < NN) g_indptr[i] = incl - v;      // exclusive within block
    if (t == 1023) g_bsum[blockIdx.x] = incl;
}

// ---------------- CSR scatter: inline bsum scan + self-detect --------------
__global__ void scatter_kernel(const long long* __restrict__ ei) {
    __shared__ int sflag;
    __shared__ int sh[128];
    __shared__ int sexc[128];
    int t = threadIdx.x;
    // per-block exclusive scan of the 98 block sums (redundant, cheap)
    if (t < 128) {
        int v = (t < NBLK) ? g_bsum[t] : 0;
        sh[t] = v;
        sexc[t] = v;    // temporarily hold own value
    }
    __syncthreads();
    #pragma unroll
    for (int off = 1; off < 128; off <<= 1) {
        int a = (t < 128 && t >= off) ? sh[t - off] : 0;
        __syncthreads();
        if (t < 128) sh[t] += a;
        __syncthreads();
    }
    if (t < 128) sexc[t] = sh[t] - sexc[t];  // exclusive prefix
    int is64 = block_detect_is64(ei, &sflag); // includes a __syncthreads
    // block 0 publishes boff + indptr[NN] fix-up for the gathers
    if (blockIdx.x == 0 && t < NBLK) {
        g_boff[t] = sexc[t];
        if (t == NBLK - 1) g_indptr[NN] = EE - sexc[t];
    }
    int e = (blockIdx.x * blockDim.x + t) * 2;
    if (e >= EE) return;
    int s0, s1, d0, d1;
    if (is64) {
        longlong2 sv = *(const longlong2*)&ei[e];
        longlong2 dv = *(const longlong2*)&ei[e + EE];
        s0 = (int)sv.x; s1 = (int)sv.y; d0 = (int)dv.x; d1 = (int)dv.y;
    } else {
        const int* p = (const int*)ei;
        int2 sv = *(const int2*)&p[e];
        int2 dv = *(const int2*)&p[e + EE];
        s0 = sv.x; s1 = sv.y; d0 = dv.x; d1 = dv.y;
    }
    int2 r = *(const int2*)&g_rank[e];
    g_indices[g_indptr[d0] + sexc[d0 >> 10] + r.x] = s0;
    g_indices[g_indptr[d1] + sexc[d1 >> 10] + r.y] = s1;
}

// ---------------- GEMM1 via HMMA (fp16 in, fp32 accum) + fused als1/ald1 ---
__global__ __launch_bounds__(256)
void gemm1_kernel(const float* __restrict__ x, const float* __restrict__ W,
                  const float* __restrict__ a_src, const float* __restrict__ a_dst) {
    extern __shared__ __half hsm[];
    __half* xa = hsm;                        // [128][XA_STRIDE]
    __half* wb = hsm + 128 * XA_STRIDE;      // [128][WB_STRIDE]
    int t = threadIdx.x;
    int bn = blockIdx.x * 128;
    for (int i = t; i < DIN * HD / 4; i += 256) {
        float4 v = ((const float4*)W)[i];
        int r = (i * 4) >> 6, c = (i * 4) & 63;
        __half2 h0 = __floats2half2_rn(v.x, v.y);
        __half2 h1 = __floats2half2_rn(v.z, v.w);
        *(uint2*)&wb[r * WB_STRIDE + c] = make_uint2(*(unsigned*)&h0, *(unsigned*)&h1);
    }
    for (int i = t; i < 128 * DIN / 4; i += 256) {
        int r = (i * 4) >> 7, c = (i * 4) & 127;
        int node = bn + r;
        float4 v = (node < NN) ? *(const float4*)&x[(size_t)node * DIN + c]
                               : make_float4(0.f, 0.f, 0.f, 0.f);
        __half2 h0 = __floats2half2_rn(v.x, v.y);
        __half2 h1 = __floats2half2_rn(v.z, v.w);
        *(uint2*)&xa[r * XA_STRIDE + c] = make_uint2(*(unsigned*)&h0, *(unsigned*)&h1);
    }
    __syncthreads();

    int wid = t >> 5, lane = t & 31;
    unsigned xa_base = (unsigned)__cvta_generic_to_shared(xa);
    unsigned wb_base = (unsigned)__cvta_generic_to_shared(wb);
    float c[8][4];
    #pragma unroll
    for (int nt = 0; nt < 8; nt++)
        c[nt][0] = c[nt][1] = c[nt][2] = c[nt][3] = 0.f;

    int mrow = (lane & 7) + ((lane >> 3) & 1) * 8;
    int mcol = (lane >> 4) * 8;
    int brow = (lane & 7) + ((lane >> 3) & 1) * 8;
    #pragma unroll
    for (int ks = 0; ks < 8; ks++) {
        unsigned a0, a1, a2, a3;
        unsigned a_addr = xa_base +
            ((unsigned)((wid * 16 + mrow) * XA_STRIDE + ks * 16 + mcol) << 1);
        ldsm_x4(a0, a1, a2, a3, a_addr);
        unsigned b_row_addr = wb_base +
            ((unsigned)((ks * 16 + brow) * WB_STRIDE) << 1);
        #pragma unroll
        for (int nt = 0; nt < 8; nt++) {
            unsigned b0, b1;
            ldsm_x2t(b0, b1, b_row_addr + (unsigned)(nt * 16));
            mma16816(c[nt], a0, a1, a2, a3, b0, b1);
        }
    }

    int q = lane & 3;
    int r0 = wid * 16 + (lane >> 2);
    int node0 = bn + r0, node1 = node0 + 8;
    bool ok0 = node0 < NN, ok1 = node1 < NN;
    #pragma unroll
    for (int nt = 0; nt < 8; nt++) {
        int col = nt * 8 + q * 2;
        if (ok0) {
            __half2 p = __floats2half2_rn(c[nt][0], c[nt][1]);
            *(__half2*)&g_h1h[(size_t)node0 * HD + col] = p;
        }
        if (ok1) {
            __half2 p = __floats2half2_rn(c[nt][2], c[nt][3]);
            *(__half2*)&g_h1h[(size_t)node1 * HD + col] = p;
        }
    }
    float ps0[4], pd0[4], ps1[4], pd1[4];
    #pragma unroll
    for (int h = 0; h < 4; h++) {
        int i0 = h * 16 + q * 2;
        int i2 = h * 16 + 8 + q * 2;
        float2 sa = *(const float2*)&a_src[i0];
        float2 sb = *(const float2*)&a_src[i2];
        float2 da = *(const float2*)&a_dst[i0];
        float2 db = *(const float2*)&a_dst[i2];
        int n0 = 2 * h, n1 = 2 * h + 1;
        ps0[h] = c[n0][0]*sa.x + c[n0][1]*sa.y + c[n1][0]*sb.x + c[n1][1]*sb.y;
        pd0[h] = c[n0][0]*da.x + c[n0][1]*da.y + c[n1][0]*db.x + c[n1][1]*db.y;
        ps1[h] = c[n0][2]*sa.x + c[n0][3]*sa.y + c[n1][2]*sb.x + c[n1][3]*sb.y;
        pd1[h] = c[n0][2]*da.x + c[n0][3]*da.y + c[n1][2]*db.x + c[n1][3]*db.y;
    }
    #pragma unroll
    for (int off = 1; off < 4; off <<= 1) {
        #pragma unroll
        for (int h = 0; h < 4; h++) {
            ps0[h] += __shfl_xor_sync(FULLM, ps0[h], off);
            pd0[h] += __shfl_xor_sync(FULLM, pd0[h], off);
            ps1[h] += __shfl_xor_sync(FULLM, ps1[h], off);
            pd1[h] += __shfl_xor_sync(FULLM, pd1[h], off);
        }
    }
    if (q == 0) {
        if (ok0) {
            *(float4*)&g_als1[node0 * 4] = make_float4(ps0[0], ps0[1], ps0[2], ps0[3]);
            *(float4*)&g_ald1[node0 * 4] = make_float4(pd0[0], pd0[1], pd0[2], pd0[3]);
        }
        if (ok1) {
            *(float4*)&g_als1[node1 * 4] = make_float4(ps1[0], ps1[1], ps1[2], ps1[3]);
            *(float4*)&g_ald1[node1 * 4] = make_float4(pd1[0], pd1[1], pd1[2], pd1[3]);
        }
    }
}

// ---------------- FUSED gather1: 4 nodes/warp (8-lane quarter per node) ----
__global__ void gather1_fused_kernel(const float* __restrict__ b1,
                                     const float* __restrict__ W2,
                                     const float* __restrict__ a_src2,
                                     const float* __restrict__ a_dst2) {
    int w = (blockIdx.x * blockDim.x + threadIdx.x) >> 5;
    if (w * 4 >= NN) return;
    int lane = threadIdx.x & 31;
    int q = lane >> 3, m = lane & 7;
    int n = 4 * w + q;                       // NN % 4 == 0 -> always valid
    int myh = m >> 1;
    float ad = g_ald1[n * 4 + myh];
    float ax[8];
    #pragma unroll
    for (int i = 0; i < 8; i++) ax[i] = 0.f;
    float z = 0.f;
    {   // self loop
        float w0 = lrelu_exp(g_als1[n * 4 + myh] + ad);
        z += w0;
        uint4 u = *(const uint4*)&g_h1h[(size_t)n * HD + m * 8];
        float2 p0 = __half22float2(*(__half2*)&u.x);
        float2 p1 = __half22float2(*(__half2*)&u.y);
        float2 p2 = __half22float2(*(__half2*)&u.z);
        float2 p3 = __half22float2(*(__half2*)&u.w);
        ax[0] += p0.x*w0; ax[1] += p0.y*w0; ax[2] += p1.x*w0; ax[3] += p1.y*w0;
        ax[4] += p2.x*w0; ax[5] += p2.y*w0; ax[6] += p3.x*w0; ax[7] += p3.y*w0;
    }
    int e   = g_indptr[n]     + g_boff[n >> 10];
    int end = g_indptr[n + 1] + g_boff[(n + 1) >> 10];
    for (; e + 4 <= end; e += 4) {
        int s0 = g_indices[e],     s1 = g_indices[e + 1];
        int s2 = g_indices[e + 2], s3 = g_indices[e + 3];
        float l0 = g_als1[s0 * 4 + myh], l1 = g_als1[s1 * 4 + myh];
        float l2 = g_als1[s2 * 4 + myh], l3 = g_als1[s3 * 4 + myh];
        uint4 u0 = *(const uint4*)&g_h1h[(size_t)s0 * HD + m * 8];
        uint4 u1 = *(const uint4*)&g_h1h[(size_t)s1 * HD + m * 8];
        uint4 u2 = *(const uint4*)&g_h1h[(size_t)s2 * HD + m * 8];
        uint4 u3 = *(const uint4*)&g_h1h[(size_t)s3 * HD + m * 8];
        float w0 = lrelu_exp(l0 + ad), w1 = lrelu_exp(l1 + ad);
        float w2 = lrelu_exp(l2 + ad), w3 = lrelu_exp(l3 + ad);
        z += (w0 + w1) + (w2 + w3);
        float2 q0 = __half22float2(*(__half2*)&u0.x), q1 = __half22float2(*(__half2*)&u0.y);
        float2 q2 = __half22float2(*(__half2*)&u0.z), q3 = __half22float2(*(__half2*)&u0.w);
        float2 r0 = __half22float2(*(__half2*)&u1.x), r1 = __half22float2(*(__half2*)&u1.y);
        float2 r2 = __half22float2(*(__half2*)&u1.z), r3 = __half22float2(*(__half2*)&u1.w);
        float2 t0 = __half22float2(*(__half2*)&u2.x), t1 = __half22float2(*(__half2*)&u2.y);
        float2 t2 = __half22float2(*(__half2*)&u2.z), t3 = __half22float2(*(__half2*)&u2.w);
        float2 v0 = __half22float2(*(__half2*)&u3.x), v1 = __half22float2(*(__half2*)&u3.y);
        float2 v2 = __half22float2(*(__half2*)&u3.z), v3 = __half22float2(*(__half2*)&u3.w);
        ax[0] += q0.x*w0 + r0.x*w1 + t0.x*w2 + v0.x*w3;
        ax[1] += q0.y*w0 + r0.y*w1 + t0.y*w2 + v0.y*w3;
        ax[2] += q1.x*w0 + r1.x*w1 + t1.x*w2 + v1.x*w3;
        ax[3] += q1.y*w0 + r1.y*w1 + t1.y*w2 + v1.y*w3;
        ax[4] += q2.x*w0 + r2.x*w1 + t2.x*w2 + v2.x*w3;
        ax[5] += q2.y*w0 + r2.y*w1 + t2.y*w2 + v2.y*w3;
        ax[6] += q3.x*w0 + r3.x*w1 + t3.x*w2 + v3.x*w3;
        ax[7] += q3.y*w0 + r3.y*w1 + t3.y*w2 + v3.y*w3;
    }
    for (; e < end; e++) {
        int s = g_indices[e];
        float l = g_als1[s * 4 + myh];
        uint4 u = *(const uint4*)&g_h1h[(size_t)s * HD + m * 8];
        float w0 = lrelu_exp(l + ad);
        z += w0;
        float2 p0 = __half22float2(*(__half2*)&u.x);
        float2 p1 = __half22float2(*(__half2*)&u.y);
        float2 p2 = __half22float2(*(__half2*)&u.z);
        float2 p3 = __half22float2(*(__half2*)&u.w);
        ax[0] += p0.x*w0; ax[1] += p0.y*w0; ax[2] += p1.x*w0; ax[3] += p1.y*w0;
        ax[4] += p2.x*w0; ax[5] += p2.y*w0; ax[6] += p3.x*w0; ax[7] += p3.y*w0;
    }
    __syncwarp();                            // re-converge before shfl epilogue
    float zi = 1.f / (z + 1e-16f);
    float4 bb0 = *(const float4*)&b1[m * 8];
    float4 bb1 = *(const float4*)&b1[m * 8 + 4];
    float f[8];
    f[0] = ax[0]*zi + bb0.x; f[1] = ax[1]*zi + bb0.y;
    f[2] = ax[2]*zi + bb0.z; f[3] = ax[3]*zi + bb0.w;
    f[4] = ax[4]*zi + bb1.x; f[5] = ax[5]*zi + bb1.y;
    f[6] = ax[6]*zi + bb1.z; f[7] = ax[7]*zi + bb1.w;
    #pragma unroll
    for (int i = 0; i < 8; i++) f[i] = f[i] > 0.f ? f[i] : expm1f(f[i]);  // ELU
    // ---- fused GEMV: lane computes output channels m*4..m*4+3 -------------
    float t0 = 0.f, t1 = 0.f, t2 = 0.f, t3 = 0.f;
    int qb = lane & 24;   // quarter base for shfl source
    #pragma unroll
    for (int k = 0; k < 8; k++) {
        #pragma unroll
        for (int j = 0; j < 8; j++) {
            float g = __shfl_sync(FULLM, f[j], qb + k);   // feat channel 8k+j of my node
            float4 wv = __ldg(&((const float4*)W2)[(8 * k + j) * 8 + m]);
            t0 += g * wv.x; t1 += g * wv.y; t2 += g * wv.z; t3 += g * wv.w;
        }
    }
    __half2 tp0 = __floats2half2_rn(t0, t1);
    __half2 tp1 = __floats2half2_rn(t2, t3);
    *(uint2*)&g_t2h[(size_t)n * DOUT + m * 4] = make_uint2(*(unsigned*)&tp0, *(unsigned*)&tp1);
    // ---- fused als2/ald2 (fp32 exact), reduce within quarter --------------
    float4 s2 = __ldg(&((const float4*)a_src2)[m]);
    float4 d2 = __ldg(&((const float4*)a_dst2)[m]);
    float ps = t0*s2.x + t1*s2.y + t2*s2.z + t3*s2.w;
    float pd = t0*d2.x + t1*d2.y + t2*d2.z + t3*d2.w;
    #pragma unroll
    for (int off = 1; off < 8; off <<= 1) {
        ps += __shfl_xor_sync(FULLM, ps, off);
        pd += __shfl_xor_sync(FULLM, pd, off);
    }
    if (m == 0) { g_als2[n] = ps; g_ald2[n] = pd; }
}

// ---------------- gather2: 8 nodes/warp (4-lane group per node) ------------
__global__ void gather2_kernel(float* __restrict__ out, const float* __restrict__ b2) {
    int w = (blockIdx.x * blockDim.x + threadIdx.x) >> 5;
    if (w * 8 >= NN) return;
    int lane = threadIdx.x & 31;
    int g = lane >> 2, ml = lane & 3;
    int n = 8 * w + g;                       // NN % 8 == 0 -> always valid
    float ad = g_ald2[n];
    float a0 = 0.f, a1 = 0.f, a2 = 0.f, a3 = 0.f;
    float a4 = 0.f, a5 = 0.f, a6 = 0.f, a7 = 0.f, z = 0.f;
    {   // self loop
        float w0 = lrelu_exp(g_als2[n] + ad);
        z += w0;
        uint4 u = *(const uint4*)&g_t2h[(size_t)n * DOUT + ml * 8];
        float2 p0 = __half22float2(*(__half2*)&u.x);
        float2 p1 = __half22float2(*(__half2*)&u.y);
        float2 p2 = __half22float2(*(__half2*)&u.z);
        float2 p3 = __half22float2(*(__half2*)&u.w);
        a0 += p0.x*w0; a1 += p0.y*w0; a2 += p1.x*w0; a3 += p1.y*w0;
        a4 += p2.x*w0; a5 += p2.y*w0; a6 += p3.x*w0; a7 += p3.y*w0;
    }
    int e   = g_indptr[n]     + g_boff[n >> 10];
    int end = g_indptr[n + 1] + g_boff[(n + 1) >> 10];
    for (; e + 4 <= end; e += 4) {
        int s0 = g_indices[e],     s1 = g_indices[e + 1];
        int s2 = g_indices[e + 2], s3 = g_indices[e + 3];
        float l0 = g_als2[s0], l1 = g_als2[s1], l2 = g_als2[s2], l3 = g_als2[s3];
        uint4 u0 = *(const uint4*)&g_t2h[(size_t)s0 * DOUT + ml * 8];
        uint4 u1 = *(const uint4*)&g_t2h[(size_t)s1 * DOUT + ml * 8];
        uint4 u2 = *(const uint4*)&g_t2h[(size_t)s2 * DOUT + ml * 8];
        uint4 u3 = *(const uint4*)&g_t2h[(size_t)s3 * DOUT + ml * 8];
        float w0 = lrelu_exp(l0 + ad), w1 = lrelu_exp(l1 + ad);
        float w2 = lrelu_exp(l2 + ad), w3 = lrelu_exp(l3 + ad);
        z += (w0 + w1) + (w2 + w3);
        float2 q0 = __half22float2(*(__half2*)&u0.x), q1 = __half22float2(*(__half2*)&u0.y);
        float2 q2 = __half22float2(*(__half2*)&u0.z), q3 = __half22float2(*(__half2*)&u0.w);
        float2 r0 = __half22float2(*(__half2*)&u1.x), r1 = __half22float2(*(__half2*)&u1.y);
        float2 r2 = __half22float2(*(__half2*)&u1.z), r3 = __half22float2(*(__half2*)&u1.w);
        float2 t0 = __half22float2(*(__half2*)&u2.x), t1 = __half22float2(*(__half2*)&u2.y);
        float2 t2 = __half22float2(*(__half2*)&u2.z), t3 = __half22float2(*(__half2*)&u2.w);
        float2 v0 = __half22float2(*(__half2*)&u3.x), v1 = __half22float2(*(__half2*)&u3.y);
        float2 v2 = __half22float2(*(__half2*)&u3.z), v3 = __half22float2(*(__half2*)&u3.w);
        a0 += q0.x*w0 + r0.x*w1 + t0.x*w2 + v0.x*w3;
        a1 += q0.y*w0 + r0.y*w1 + t0.y*w2 + v0.y*w3;
        a2 += q1.x*w0 + r1.x*w1 + t1.x*w2 + v1.x*w3;
        a3 += q1.y*w0 + r1.y*w1 + t1.y*w2 + v1.y*w3;
        a4 += q2.x*w0 + r2.x*w1 + t2.x*w2 + v2.x*w3;
        a5 += q2.y*w0 + r2.y*w1 + t2.y*w2 + v2.y*w3;
        a6 += q3.x*w0 + r3.x*w1 + t3.x*w2 + v3.x*w3;
        a7 += q3.y*w0 + r3.y*w1 + t3.y*w2 + v3.y*w3;
    }
    for (; e < end; e++) {
        int s = g_indices[e];
        float l = g_als2[s];
        uint4 u = *(const uint4*)&g_t2h[(size_t)s * DOUT + ml * 8];
        float w0 = lrelu_exp(l + ad);
        z += w0;
        float2 p0 = __half22float2(*(__half2*)&u.x);
        float2 p1 = __half22float2(*(__half2*)&u.y);
        float2 p2 = __half22float2(*(__half2*)&u.z);
        float2 p3 = __half22float2(*(__half2*)&u.w);
        a0 += p0.x*w0; a1 += p0.y*w0; a2 += p1.x*w0; a3 += p1.y*w0;
        a4 += p2.x*w0; a5 += p2.y*w0; a6 += p3.x*w0; a7 += p3.y*w0;
    }
    float zi = 1.f / (z + 1e-16f);
    float4 bb0 = *(const float4*)&b2[ml * 8];
    float4 bb1 = *(const float4*)&b2[ml * 8 + 4];
    float* op = &out[(size_t)n * DOUT + ml * 8];
    *(float4*)op       = make_float4(a0 * zi + bb0.x, a1 * zi + bb0.y,
                                     a2 * zi + bb0.z, a3 * zi + bb0.w);
    *(float4*)(op + 4) = make_float4(a4 * zi + bb1.x, a5 * zi + bb1.y,
                                     a6 * zi + bb1.z, a7 * zi + bb1.w);
}

// ---------------------------------------------------------------------------
extern "C" void kernel_launch(void* const* d_in, const int* in_sizes, int n_in,
                              void* d_out, int out_size) {
    const float*     x      = (const float*)d_in[0];
    const long long* ei     = (const long long*)d_in[1];
    const float*     W1     = (const float*)d_in[2];
    const float*     a_src1 = (const float*)d_in[3];
    const float*     a_dst1 = (const float*)d_in[4];
    const float*     b1     = (const float*)d_in[5];
    const float*     W2     = (const float*)d_in[6];
    const float*     a_src2 = (const float*)d_in[7];
    const float*     a_dst2 = (const float*)d_in[8];
    const float*     b2     = (const float*)d_in[9];
    float* out = (float*)d_out;

    const int GB  = (NN + 127) / 128;
    const int E2  = (EE / 2 + 255) / 256;
    const int WB1 = ((NN / 4) * 32 + 255) / 256;   // 4 nodes per warp
    const int WB2 = ((NN / 8) * 32 + 255) / 256;   // 8 nodes per warp

    // zero degree counters via memset node (not a kernel launch)
    void* cntPtr = nullptr;
    cudaGetSymbolAddress(&cntPtr, g_cnt);
    cudaMemsetAsync(cntPtr, 0, NN * sizeof(int), 0);

    cudaEventRecord(g_evFork, 0);
    cudaStreamWaitEvent(g_s2, g_evFork, 0);

    convert_count_kernel<<<E2, 256>>>(ei);
    scan1_kernel<<<NBLK, 1024>>>();
    gemm1_kernel<<<GB, 256, G1_SMEM, g_s2>>>(x, W1, a_src1, a_dst1);
    cudaEventRecord(g_evJoin, g_s2);
    scatter_kernel<<<E2, 256>>>(ei);

    cudaStreamWaitEvent(0, g_evJoin, 0);
    gather1_fused_kernel<<<WB1, 256>>>(b1, W2, a_src2, a_dst2);
    gather2_kernel<<<WB2, 256>>>(out, b2);
}